// round 7
// baseline (speedup 1.0000x reference)
#include <cuda_runtime.h>
#include <cuda_fp16.h>

// Fixed shapes for SPHERE_CUDA_77163382440039
static constexpr int HW  = 512 * 512;   // 262144 HT cells
static constexpr int NCH = 128;         // flat channels (B4 * C4)
static constexpr int S   = 32768;       // sphere bins
static constexpr int CAP = 128;         // bucket capacity per bin (Poisson(45.8))

// Scratch (static __device__ — no runtime allocation)
__device__ __align__(16) __half g_xTh[(size_t)HW * NCH];     // x transposed [hw][ch], fp16, 67 MB
__device__ __align__(16) float2 g_bucket[(size_t)S * CAP];   // (h bits, weight) per bin, 33.5 MB
__device__ int g_cursor[S];

// ---------------------------------------------------------------------------
__global__ void zero_cursor_kernel() {
    int i = blockIdx.x * blockDim.x + threadIdx.x;
    if (i < S) g_cursor[i] = 0;
}

// ---------------------------------------------------------------------------
// Transpose + convert: x [128][HW] fp32 -> g_xTh [HW][128] fp16.
// Tile = 32 ch x 128 hw. Phase 1: float4 global reads (512B warp runs) ->
// conflict-free 16B smem stores at XOR-swizzled column. Phase 2: conflict-free
// scalar smem reads -> 16B global stores in 64B full-sector runs.
__global__ __launch_bounds__(256) void transpose_convert_kernel(const float* __restrict__ in) {
    __shared__ float4 tile4[32][32];    // 16 KB, [ch][swizzled hw4]
    const int t  = threadIdx.x;
    const int h0 = blockIdx.x * 128;
    const int r0 = blockIdx.y * 32;

    #pragma unroll
    for (int k = 0; k < 4; k++) {
        int ch_l = (t >> 5) + k * 8;
        int hw4  = t & 31;
        float4 v = *reinterpret_cast<const float4*>(
            &in[(size_t)(r0 + ch_l) * HW + h0 + hw4 * 4]);
        tile4[ch_l][hw4 ^ (((ch_l >> 3) & 3) << 1)] = v;
    }
    __syncthreads();

    const float* tf = reinterpret_cast<const float*>(tile4);
    #pragma unroll
    for (int k = 0; k < 2; k++) {
        int chg  = t & 3;                               // group of 8 channels
        int hw_l = (t >> 5) * 8 + ((t & 31) >> 2) + k * 64;
        int swz  = (chg << 1);
        int col  = ((hw_l >> 2) ^ swz) * 4 + (hw_l & 3);
        float f0 = tf[(chg * 8 + 0) * 128 + col];
        float f1 = tf[(chg * 8 + 1) * 128 + col];
        float f2 = tf[(chg * 8 + 2) * 128 + col];
        float f3 = tf[(chg * 8 + 3) * 128 + col];
        float f4 = tf[(chg * 8 + 4) * 128 + col];
        float f5 = tf[(chg * 8 + 5) * 128 + col];
        float f6 = tf[(chg * 8 + 6) * 128 + col];
        float f7 = tf[(chg * 8 + 7) * 128 + col];
        __half2 h0p = __floats2half2_rn(f0, f1);
        __half2 h1p = __floats2half2_rn(f2, f3);
        __half2 h2p = __floats2half2_rn(f4, f5);
        __half2 h3p = __floats2half2_rn(f6, f7);
        uint4 pk;
        pk.x = *reinterpret_cast<const unsigned*>(&h0p);
        pk.y = *reinterpret_cast<const unsigned*>(&h1p);
        pk.z = *reinterpret_cast<const unsigned*>(&h2p);
        pk.w = *reinterpret_cast<const unsigned*>(&h3p);
        *reinterpret_cast<uint4*>(
            &g_xTh[(size_t)(h0 + hw_l) * NCH + r0 + chg * 8]) = pk;
    }
}

// ---------------------------------------------------------------------------
// Bucket votes by sphere bin: 4 votes per thread, vectorized index loads.
__global__ void scatter_kernel(const int* __restrict__ ht_idx,
                               const int* __restrict__ sp_idx,
                               const float* __restrict__ weight,
                               int nvotes) {
    int v0 = (blockIdx.x * blockDim.x + threadIdx.x) * 4;
    if (v0 >= nvotes) return;
    if (v0 + 4 <= nvotes) {
        int4   h  = *reinterpret_cast<const int4*>(&ht_idx[v0]);
        int4   sp = *reinterpret_cast<const int4*>(&sp_idx[v0]);
        float4 w4 = *reinterpret_cast<const float4*>(&weight[v0]);
        int p0 = atomicAdd(&g_cursor[sp.x], 1);
        int p1 = atomicAdd(&g_cursor[sp.y], 1);
        int p2 = atomicAdd(&g_cursor[sp.z], 1);
        int p3 = atomicAdd(&g_cursor[sp.w], 1);
        if (p0 < CAP) g_bucket[(size_t)sp.x * CAP + p0] = make_float2(__int_as_float(h.x), w4.x);
        if (p1 < CAP) g_bucket[(size_t)sp.y * CAP + p1] = make_float2(__int_as_float(h.y), w4.y);
        if (p2 < CAP) g_bucket[(size_t)sp.z * CAP + p2] = make_float2(__int_as_float(h.z), w4.z);
        if (p3 < CAP) g_bucket[(size_t)sp.w * CAP + p3] = make_float2(__int_as_float(h.w), w4.w);
    } else {
        for (int v = v0; v < nvotes; v++) {
            int s   = sp_idx[v];
            int pos = atomicAdd(&g_cursor[s], 1);
            if (pos < CAP)
                g_bucket[(size_t)s * CAP + pos] =
                    make_float2(__int_as_float(ht_idx[v]), weight[v]);
        }
    }
}

// ---------------------------------------------------------------------------
// One warp per sphere bin; lane l owns channels [4l, 4l+4) in fp32 registers.
// Main loop: unroll-8 with float4 record loads (8 gathers in flight).
// Remainder: ONE masked unroll-8 pass (clamped indices, zeroed weights) —
// no serial dependent tail. 8 bins/block; smem-staged fused output transpose.
__global__ __launch_bounds__(256) void accum_kernel(float* __restrict__ out) {
    const int warp = threadIdx.x >> 5;
    const int lane = threadIdx.x & 31;
    const int s    = blockIdx.x * 8 + warp;

    int n = g_cursor[s];
    if (n > CAP) n = CAP;
    const float2* __restrict__ rec  = &g_bucket[(size_t)s * CAP];
    const float4* __restrict__ rec4 = reinterpret_cast<const float4*>(rec);
    const size_t col = (size_t)(lane * 4);

    float4 a0 = make_float4(0.f, 0.f, 0.f, 0.f);
    float4 a1 = make_float4(0.f, 0.f, 0.f, 0.f);

    int i = 0;
    const int nfull = n & ~7;
    for (; i < nfull; i += 8) {
        float4 ra = rec4[(i >> 1) + 0];
        float4 rb = rec4[(i >> 1) + 1];
        float4 rc = rec4[(i >> 1) + 2];
        float4 rd = rec4[(i >> 1) + 3];
        const uint2 p0 = *reinterpret_cast<const uint2*>(
            &g_xTh[(size_t)__float_as_int(ra.x) * NCH + col]);
        const uint2 p1 = *reinterpret_cast<const uint2*>(
            &g_xTh[(size_t)__float_as_int(ra.z) * NCH + col]);
        const uint2 p2 = *reinterpret_cast<const uint2*>(
            &g_xTh[(size_t)__float_as_int(rb.x) * NCH + col]);
        const uint2 p3 = *reinterpret_cast<const uint2*>(
            &g_xTh[(size_t)__float_as_int(rb.z) * NCH + col]);
        const uint2 p4 = *reinterpret_cast<const uint2*>(
            &g_xTh[(size_t)__float_as_int(rc.x) * NCH + col]);
        const uint2 p5 = *reinterpret_cast<const uint2*>(
            &g_xTh[(size_t)__float_as_int(rc.z) * NCH + col]);
        const uint2 p6 = *reinterpret_cast<const uint2*>(
            &g_xTh[(size_t)__float_as_int(rd.x) * NCH + col]);
        const uint2 p7 = *reinterpret_cast<const uint2*>(
            &g_xTh[(size_t)__float_as_int(rd.z) * NCH + col]);

        float2 f;
        f = __half22float2(*reinterpret_cast<const __half2*>(&p0.x));
        a0.x += f.x * ra.y; a0.y += f.y * ra.y;
        f = __half22float2(*reinterpret_cast<const __half2*>(&p0.y));
        a0.z += f.x * ra.y; a0.w += f.y * ra.y;
        f = __half22float2(*reinterpret_cast<const __half2*>(&p1.x));
        a1.x += f.x * ra.w; a1.y += f.y * ra.w;
        f = __half22float2(*reinterpret_cast<const __half2*>(&p1.y));
        a1.z += f.x * ra.w; a1.w += f.y * ra.w;

        f = __half22float2(*reinterpret_cast<const __half2*>(&p2.x));
        a0.x += f.x * rb.y; a0.y += f.y * rb.y;
        f = __half22float2(*reinterpret_cast<const __half2*>(&p2.y));
        a0.z += f.x * rb.y; a0.w += f.y * rb.y;
        f = __half22float2(*reinterpret_cast<const __half2*>(&p3.x));
        a1.x += f.x * rb.w; a1.y += f.y * rb.w;
        f = __half22float2(*reinterpret_cast<const __half2*>(&p3.y));
        a1.z += f.x * rb.w; a1.w += f.y * rb.w;

        f = __half22float2(*reinterpret_cast<const __half2*>(&p4.x));
        a0.x += f.x * rc.y; a0.y += f.y * rc.y;
        f = __half22float2(*reinterpret_cast<const __half2*>(&p4.y));
        a0.z += f.x * rc.y; a0.w += f.y * rc.y;
        f = __half22float2(*reinterpret_cast<const __half2*>(&p5.x));
        a1.x += f.x * rc.w; a1.y += f.y * rc.w;
        f = __half22float2(*reinterpret_cast<const __half2*>(&p5.y));
        a1.z += f.x * rc.w; a1.w += f.y * rc.w;

        f = __half22float2(*reinterpret_cast<const __half2*>(&p6.x));
        a0.x += f.x * rd.y; a0.y += f.y * rd.y;
        f = __half22float2(*reinterpret_cast<const __half2*>(&p6.y));
        a0.z += f.x * rd.y; a0.w += f.y * rd.y;
        f = __half22float2(*reinterpret_cast<const __half2*>(&p7.x));
        a1.x += f.x * rd.w; a1.y += f.y * rd.w;
        f = __half22float2(*reinterpret_cast<const __half2*>(&p7.y));
        a1.z += f.x * rd.w; a1.w += f.y * rd.w;
    }

    // Masked epilogue: one overlapped unroll-8 pass, no serial tail.
    if (i < n) {
        #pragma unroll
        for (int j = 0; j < 8; j++) {
            int idx = i + j;
            int cl  = idx < n ? idx : n - 1;
            float2 r0 = rec[cl];
            float wt  = idx < n ? r0.y : 0.f;
            const uint2 p0 = *reinterpret_cast<const uint2*>(
                &g_xTh[(size_t)__float_as_int(r0.x) * NCH + col]);
            float2 f;
            f = __half22float2(*reinterpret_cast<const __half2*>(&p0.x));
            a0.x += f.x * wt; a0.y += f.y * wt;
            f = __half22float2(*reinterpret_cast<const __half2*>(&p0.y));
            a0.z += f.x * wt; a0.w += f.y * wt;
        }
    }
    a0.x += a1.x; a0.y += a1.y; a0.z += a1.z; a0.w += a1.w;

    // Stage [8 bins][128 ch] in smem, then write out[ch][s0..s0+7] coalesced.
    __shared__ float sm[8][128];
    *reinterpret_cast<float4*>(&sm[warp][lane * 4]) = a0;
    __syncthreads();

    if (threadIdx.x < 128) {
        const int ch = threadIdx.x;
        const int s0 = blockIdx.x * 8;
        float4 o0 = make_float4(sm[0][ch], sm[1][ch], sm[2][ch], sm[3][ch]);
        float4 o1 = make_float4(sm[4][ch], sm[5][ch], sm[6][ch], sm[7][ch]);
        float4* dst = reinterpret_cast<float4*>(&out[(size_t)ch * S + s0]);
        dst[0] = o0;
        dst[1] = o1;
    }
}

// ---------------------------------------------------------------------------
extern "C" void kernel_launch(void* const* d_in, const int* in_sizes, int n_in,
                              void* d_out, int out_size) {
    const float* x      = (const float*)d_in[0];  // [128][262144] flat
    const int*   ht     = (const int*)d_in[1];
    const int*   sp     = (const int*)d_in[2];
    const float* w      = (const float*)d_in[3];
    float*       out    = (float*)d_out;          // [128][32768] flat
    const int    nvotes = in_sizes[1];

    // 1) Zero bucket cursors.
    zero_cursor_kernel<<<(S + 255) / 256, 256>>>();

    // 2) Swizzled transpose + fp16-convert x -> g_xTh [HW][128].
    {
        dim3 grid(HW / 128, NCH / 32);   // (2048, 4)
        transpose_convert_kernel<<<grid, 256>>>(x);
    }

    // 3) Bucket votes by sphere bin (4 votes/thread).
    {
        int nthreads = (nvotes + 3) / 4;
        scatter_kernel<<<(nthreads + 255) / 256, 256>>>(ht, sp, w, nvotes);
    }

    // 4) Per-bin register accumulation (fp16 gather, fp32 accum, MLP=8,
    //    masked epilogue) + fused output transpose.
    accum_kernel<<<S / 8, 256>>>(out);
}

// round 8
// speedup vs baseline: 1.0545x; 1.0545x over previous
#include <cuda_runtime.h>
#include <cuda_fp16.h>

// Fixed shapes for SPHERE_CUDA_77163382440039
static constexpr int HW  = 512 * 512;   // 262144 HT cells
static constexpr int NCH = 128;         // flat channels (B4 * C4)
static constexpr int S   = 32768;       // sphere bins
static constexpr int CAP = 128;         // bucket capacity per bin (Poisson(45.8))

// Scratch (static __device__ — no runtime allocation)
__device__ __align__(16) __half g_xTh[(size_t)HW * NCH];     // x transposed [hw][ch], fp16, 67 MB
__device__ __align__(16) float2 g_bucket[(size_t)S * CAP];   // (h bits, weight) per bin, 33.5 MB
__device__ int g_cursor[S];

// ---------------------------------------------------------------------------
__global__ void zero_cursor_kernel() {
    int i = blockIdx.x * blockDim.x + threadIdx.x;
    if (i < S) g_cursor[i] = 0;
}

// ---------------------------------------------------------------------------
// Transpose + convert: x [128][HW] fp32 -> g_xTh [HW][128] fp16.
// Tile = 32 ch x 128 hw. Phase 1: float4 global reads (512B warp runs) ->
// conflict-free 16B smem stores at XOR-swizzled column. Phase 2: conflict-free
// scalar smem reads -> 16B global stores in 64B full-sector runs.
__global__ __launch_bounds__(256) void transpose_convert_kernel(const float* __restrict__ in) {
    __shared__ float4 tile4[32][32];    // 16 KB, [ch][swizzled hw4]
    const int t  = threadIdx.x;
    const int h0 = blockIdx.x * 128;
    const int r0 = blockIdx.y * 32;

    #pragma unroll
    for (int k = 0; k < 4; k++) {
        int ch_l = (t >> 5) + k * 8;
        int hw4  = t & 31;
        float4 v = *reinterpret_cast<const float4*>(
            &in[(size_t)(r0 + ch_l) * HW + h0 + hw4 * 4]);
        tile4[ch_l][hw4 ^ (((ch_l >> 3) & 3) << 1)] = v;
    }
    __syncthreads();

    const float* tf = reinterpret_cast<const float*>(tile4);
    #pragma unroll
    for (int k = 0; k < 2; k++) {
        int chg  = t & 3;                               // group of 8 channels
        int hw_l = (t >> 5) * 8 + ((t & 31) >> 2) + k * 64;
        int swz  = (chg << 1);
        int col  = ((hw_l >> 2) ^ swz) * 4 + (hw_l & 3);
        float f0 = tf[(chg * 8 + 0) * 128 + col];
        float f1 = tf[(chg * 8 + 1) * 128 + col];
        float f2 = tf[(chg * 8 + 2) * 128 + col];
        float f3 = tf[(chg * 8 + 3) * 128 + col];
        float f4 = tf[(chg * 8 + 4) * 128 + col];
        float f5 = tf[(chg * 8 + 5) * 128 + col];
        float f6 = tf[(chg * 8 + 6) * 128 + col];
        float f7 = tf[(chg * 8 + 7) * 128 + col];
        __half2 h0p = __floats2half2_rn(f0, f1);
        __half2 h1p = __floats2half2_rn(f2, f3);
        __half2 h2p = __floats2half2_rn(f4, f5);
        __half2 h3p = __floats2half2_rn(f6, f7);
        uint4 pk;
        pk.x = *reinterpret_cast<const unsigned*>(&h0p);
        pk.y = *reinterpret_cast<const unsigned*>(&h1p);
        pk.z = *reinterpret_cast<const unsigned*>(&h2p);
        pk.w = *reinterpret_cast<const unsigned*>(&h3p);
        *reinterpret_cast<uint4*>(
            &g_xTh[(size_t)(h0 + hw_l) * NCH + r0 + chg * 8]) = pk;
    }
}

// ---------------------------------------------------------------------------
// Bucket votes by sphere bin: one thread per vote (R6-proven version).
__global__ void scatter_kernel(const int* __restrict__ ht_idx,
                               const int* __restrict__ sp_idx,
                               const float* __restrict__ weight,
                               int nvotes) {
    int v = blockIdx.x * blockDim.x + threadIdx.x;
    if (v >= nvotes) return;
    int s   = sp_idx[v];
    int pos = atomicAdd(&g_cursor[s], 1);
    if (pos < CAP) {
        g_bucket[(size_t)s * CAP + pos] =
            make_float2(__int_as_float(ht_idx[v]), weight[v]);
    }
}

// ---------------------------------------------------------------------------
// One warp per sphere bin; lane l owns channels [4l, 4l+4) in fp32 registers.
// Main loop: unroll-8 (8 independent gathers in flight) with SOFTWARE-
// PIPELINED rec4 loads — next iteration's records prefetched while current
// gathers/FMAs execute, removing the rec->gather serial hop per iteration.
// Tail: R6's short serial loop. 8 bins/block; smem-staged fused transpose.
__global__ __launch_bounds__(256) void accum_kernel(float* __restrict__ out) {
    const int warp = threadIdx.x >> 5;
    const int lane = threadIdx.x & 31;
    const int s    = blockIdx.x * 8 + warp;

    int n = g_cursor[s];
    if (n > CAP) n = CAP;
    const float2* __restrict__ rec  = &g_bucket[(size_t)s * CAP];
    const float4* __restrict__ rec4 = reinterpret_cast<const float4*>(rec);
    const size_t col = (size_t)(lane * 4);

    float4 a0 = make_float4(0.f, 0.f, 0.f, 0.f);
    float4 a1 = make_float4(0.f, 0.f, 0.f, 0.f);

    const int nfull = n & ~7;
    float4 ra, rb, rc, rd;
    if (nfull > 0) {
        ra = rec4[0]; rb = rec4[1]; rc = rec4[2]; rd = rec4[3];
    }
    for (int i = 0; i < nfull; ) {
        // Issue all 8 gathers off the (pre-arrived) records.
        const uint2 p0 = *reinterpret_cast<const uint2*>(
            &g_xTh[(size_t)__float_as_int(ra.x) * NCH + col]);
        const uint2 p1 = *reinterpret_cast<const uint2*>(
            &g_xTh[(size_t)__float_as_int(ra.z) * NCH + col]);
        const uint2 p2 = *reinterpret_cast<const uint2*>(
            &g_xTh[(size_t)__float_as_int(rb.x) * NCH + col]);
        const uint2 p3 = *reinterpret_cast<const uint2*>(
            &g_xTh[(size_t)__float_as_int(rb.z) * NCH + col]);
        const uint2 p4 = *reinterpret_cast<const uint2*>(
            &g_xTh[(size_t)__float_as_int(rc.x) * NCH + col]);
        const uint2 p5 = *reinterpret_cast<const uint2*>(
            &g_xTh[(size_t)__float_as_int(rc.z) * NCH + col]);
        const uint2 p6 = *reinterpret_cast<const uint2*>(
            &g_xTh[(size_t)__float_as_int(rd.x) * NCH + col]);
        const uint2 p7 = *reinterpret_cast<const uint2*>(
            &g_xTh[(size_t)__float_as_int(rd.z) * NCH + col]);

        i += 8;
        // Prefetch next iteration's records (overlaps with gather latency).
        float4 na, nb, nc, nd;
        if (i < nfull) {
            na = rec4[(i >> 1) + 0];
            nb = rec4[(i >> 1) + 1];
            nc = rec4[(i >> 1) + 2];
            nd = rec4[(i >> 1) + 3];
        }

        float2 f;
        f = __half22float2(*reinterpret_cast<const __half2*>(&p0.x));
        a0.x += f.x * ra.y; a0.y += f.y * ra.y;
        f = __half22float2(*reinterpret_cast<const __half2*>(&p0.y));
        a0.z += f.x * ra.y; a0.w += f.y * ra.y;
        f = __half22float2(*reinterpret_cast<const __half2*>(&p1.x));
        a1.x += f.x * ra.w; a1.y += f.y * ra.w;
        f = __half22float2(*reinterpret_cast<const __half2*>(&p1.y));
        a1.z += f.x * ra.w; a1.w += f.y * ra.w;

        f = __half22float2(*reinterpret_cast<const __half2*>(&p2.x));
        a0.x += f.x * rb.y; a0.y += f.y * rb.y;
        f = __half22float2(*reinterpret_cast<const __half2*>(&p2.y));
        a0.z += f.x * rb.y; a0.w += f.y * rb.y;
        f = __half22float2(*reinterpret_cast<const __half2*>(&p3.x));
        a1.x += f.x * rb.w; a1.y += f.y * rb.w;
        f = __half22float2(*reinterpret_cast<const __half2*>(&p3.y));
        a1.z += f.x * rb.w; a1.w += f.y * rb.w;

        f = __half22float2(*reinterpret_cast<const __half2*>(&p4.x));
        a0.x += f.x * rc.y; a0.y += f.y * rc.y;
        f = __half22float2(*reinterpret_cast<const __half2*>(&p4.y));
        a0.z += f.x * rc.y; a0.w += f.y * rc.y;
        f = __half22float2(*reinterpret_cast<const __half2*>(&p5.x));
        a1.x += f.x * rc.w; a1.y += f.y * rc.w;
        f = __half22float2(*reinterpret_cast<const __half2*>(&p5.y));
        a1.z += f.x * rc.w; a1.w += f.y * rc.w;

        f = __half22float2(*reinterpret_cast<const __half2*>(&p6.x));
        a0.x += f.x * rd.y; a0.y += f.y * rd.y;
        f = __half22float2(*reinterpret_cast<const __half2*>(&p6.y));
        a0.z += f.x * rd.y; a0.w += f.y * rd.y;
        f = __half22float2(*reinterpret_cast<const __half2*>(&p7.x));
        a1.x += f.x * rd.w; a1.y += f.y * rd.w;
        f = __half22float2(*reinterpret_cast<const __half2*>(&p7.y));
        a1.z += f.x * rd.w; a1.w += f.y * rd.w;

        ra = na; rb = nb; rc = nc; rd = nd;
    }

    // Short serial tail (<= 7 votes), R6-proven.
    for (int i = nfull; i < n; i++) {
        float2 r0 = rec[i];
        const uint2 p0 = *reinterpret_cast<const uint2*>(
            &g_xTh[(size_t)__float_as_int(r0.x) * NCH + col]);
        float2 f;
        f = __half22float2(*reinterpret_cast<const __half2*>(&p0.x));
        a0.x += f.x * r0.y; a0.y += f.y * r0.y;
        f = __half22float2(*reinterpret_cast<const __half2*>(&p0.y));
        a0.z += f.x * r0.y; a0.w += f.y * r0.y;
    }
    a0.x += a1.x; a0.y += a1.y; a0.z += a1.z; a0.w += a1.w;

    // Stage [8 bins][128 ch] in smem, then write out[ch][s0..s0+7] coalesced.
    __shared__ float sm[8][128];
    *reinterpret_cast<float4*>(&sm[warp][lane * 4]) = a0;
    __syncthreads();

    if (threadIdx.x < 128) {
        const int ch = threadIdx.x;
        const int s0 = blockIdx.x * 8;
        float4 o0 = make_float4(sm[0][ch], sm[1][ch], sm[2][ch], sm[3][ch]);
        float4 o1 = make_float4(sm[4][ch], sm[5][ch], sm[6][ch], sm[7][ch]);
        float4* dst = reinterpret_cast<float4*>(&out[(size_t)ch * S + s0]);
        dst[0] = o0;
        dst[1] = o1;
    }
}

// ---------------------------------------------------------------------------
extern "C" void kernel_launch(void* const* d_in, const int* in_sizes, int n_in,
                              void* d_out, int out_size) {
    const float* x      = (const float*)d_in[0];  // [128][262144] flat
    const int*   ht     = (const int*)d_in[1];
    const int*   sp     = (const int*)d_in[2];
    const float* w      = (const float*)d_in[3];
    float*       out    = (float*)d_out;          // [128][32768] flat
    const int    nvotes = in_sizes[1];

    // 1) Zero bucket cursors.
    zero_cursor_kernel<<<(S + 255) / 256, 256>>>();

    // 2) Swizzled transpose + fp16-convert x -> g_xTh [HW][128].
    {
        dim3 grid(HW / 128, NCH / 32);   // (2048, 4)
        transpose_convert_kernel<<<grid, 256>>>(x);
    }

    // 3) Bucket votes by sphere bin.
    scatter_kernel<<<(nvotes + 255) / 256, 256>>>(ht, sp, w, nvotes);

    // 4) Per-bin register accumulation (fp16 gather, fp32 accum, MLP=8,
    //    pipelined record prefetch) + fused output transpose.
    accum_kernel<<<S / 8, 256>>>(out);
}

// round 9
// speedup vs baseline: 1.2130x; 1.1504x over previous
#include <cuda_runtime.h>
#include <cuda_fp16.h>

// Fixed shapes for SPHERE_CUDA_77163382440039
static constexpr int HW  = 512 * 512;   // 262144 HT cells
static constexpr int NCH = 128;         // flat channels (B4 * C4)
static constexpr int S   = 32768;       // sphere bins
static constexpr int CAP = 128;         // bucket capacity per bin (Poisson(45.8))

// Scratch (static __device__ — no runtime allocation)
__device__ __align__(16) __half g_xTh[(size_t)HW * NCH];     // x transposed [hw][ch], fp16, 67 MB
__device__ __align__(16) float2 g_bucket[(size_t)S * CAP];   // (h bits, weight) per bin, 33.5 MB
__device__ int g_cursor[S];

// ---------------------------------------------------------------------------
__global__ void zero_cursor_kernel() {
    int i = blockIdx.x * blockDim.x + threadIdx.x;
    if (i < S) g_cursor[i] = 0;
}

// ---------------------------------------------------------------------------
// FUSED: transpose+convert (x [128][HW] fp32 -> g_xTh [HW][128] fp16) AND
// vote scatter (bucket by sphere bin). The two tasks touch disjoint data;
// per-block interleaving lets the scatter's dependent-chain latency hide
// under the transpose's bandwidth stream.
// Grid: 8192 blocks x 256 thr. Transpose tile = 32 ch x 128 hw per block
// (bx = bid % 2048 -> hw, by = bid / 2048 -> ch). Scatter: vpb votes/block,
// one per thread.
__global__ __launch_bounds__(256) void fused_transpose_scatter_kernel(
    const float* __restrict__ in,
    const int* __restrict__ ht_idx,
    const int* __restrict__ sp_idx,
    const float* __restrict__ weight,
    int nvotes, int vpb) {
    __shared__ float4 tile4[32][32];    // 16 KB, [ch][swizzled hw4]
    const int t  = threadIdx.x;
    const int h0 = (blockIdx.x & 2047) * 128;
    const int r0 = (blockIdx.x >> 11) * 32;

    // Phase 1a: issue transpose global loads (512B warp runs) into registers.
    float4 v0, v1, v2, v3;
    {
        int hw4 = t & 31;
        int c0  = (t >> 5);
        v0 = *reinterpret_cast<const float4*>(&in[(size_t)(r0 + c0 +  0) * HW + h0 + hw4 * 4]);
        v1 = *reinterpret_cast<const float4*>(&in[(size_t)(r0 + c0 +  8) * HW + h0 + hw4 * 4]);
        v2 = *reinterpret_cast<const float4*>(&in[(size_t)(r0 + c0 + 16) * HW + h0 + hw4 * 4]);
        v3 = *reinterpret_cast<const float4*>(&in[(size_t)(r0 + c0 + 24) * HW + h0 + hw4 * 4]);
    }

    // Phase 1b: scatter this block's votes while the loads are in flight.
    {
        int v = blockIdx.x * vpb + t;
        if (t < vpb && v < nvotes) {
            int s   = sp_idx[v];
            int pos = atomicAdd(&g_cursor[s], 1);
            if (pos < CAP) {
                g_bucket[(size_t)s * CAP + pos] =
                    make_float2(__int_as_float(ht_idx[v]), weight[v]);
            }
        }
    }

    // Phase 1c: smem stores at XOR-swizzled column (conflict-free).
    {
        int hw4 = t & 31;
        int c0  = (t >> 5);
        tile4[c0 +  0][hw4 ^ ((((c0 +  0) >> 3) & 3) << 1)] = v0;
        tile4[c0 +  8][hw4 ^ ((((c0 +  8) >> 3) & 3) << 1)] = v1;
        tile4[c0 + 16][hw4 ^ ((((c0 + 16) >> 3) & 3) << 1)] = v2;
        tile4[c0 + 24][hw4 ^ ((((c0 + 24) >> 3) & 3) << 1)] = v3;
    }
    __syncthreads();

    // Phase 2: conflict-free scalar smem reads -> pack 8 halves ->
    // 16B global stores in 64B full-sector runs.
    const float* tf = reinterpret_cast<const float*>(tile4);
    #pragma unroll
    for (int k = 0; k < 2; k++) {
        int chg  = t & 3;                               // group of 8 channels
        int hw_l = (t >> 5) * 8 + ((t & 31) >> 2) + k * 64;
        int swz  = (chg << 1);
        int col  = ((hw_l >> 2) ^ swz) * 4 + (hw_l & 3);
        float f0 = tf[(chg * 8 + 0) * 128 + col];
        float f1 = tf[(chg * 8 + 1) * 128 + col];
        float f2 = tf[(chg * 8 + 2) * 128 + col];
        float f3 = tf[(chg * 8 + 3) * 128 + col];
        float f4 = tf[(chg * 8 + 4) * 128 + col];
        float f5 = tf[(chg * 8 + 5) * 128 + col];
        float f6 = tf[(chg * 8 + 6) * 128 + col];
        float f7 = tf[(chg * 8 + 7) * 128 + col];
        __half2 h0p = __floats2half2_rn(f0, f1);
        __half2 h1p = __floats2half2_rn(f2, f3);
        __half2 h2p = __floats2half2_rn(f4, f5);
        __half2 h3p = __floats2half2_rn(f6, f7);
        uint4 pk;
        pk.x = *reinterpret_cast<const unsigned*>(&h0p);
        pk.y = *reinterpret_cast<const unsigned*>(&h1p);
        pk.z = *reinterpret_cast<const unsigned*>(&h2p);
        pk.w = *reinterpret_cast<const unsigned*>(&h3p);
        *reinterpret_cast<uint4*>(
            &g_xTh[(size_t)(h0 + hw_l) * NCH + r0 + chg * 8]) = pk;
    }
}

// ---------------------------------------------------------------------------
// One warp per sphere bin; lane l owns channels [4l, 4l+4) in fp32 registers.
// R6-proven loop: unroll-8 with float4 record loads (8 gathers in flight),
// short serial tail. 8 bins/block; smem-staged fused output transpose.
__global__ __launch_bounds__(256) void accum_kernel(float* __restrict__ out) {
    const int warp = threadIdx.x >> 5;
    const int lane = threadIdx.x & 31;
    const int s    = blockIdx.x * 8 + warp;

    int n = g_cursor[s];
    if (n > CAP) n = CAP;
    const float2* __restrict__ rec  = &g_bucket[(size_t)s * CAP];
    const float4* __restrict__ rec4 = reinterpret_cast<const float4*>(rec);
    const size_t col = (size_t)(lane * 4);

    float4 a0 = make_float4(0.f, 0.f, 0.f, 0.f);
    float4 a1 = make_float4(0.f, 0.f, 0.f, 0.f);

    int i = 0;
    for (; i + 8 <= n; i += 8) {
        float4 ra = rec4[(i >> 1) + 0];
        float4 rb = rec4[(i >> 1) + 1];
        float4 rc = rec4[(i >> 1) + 2];
        float4 rd = rec4[(i >> 1) + 3];
        const uint2 p0 = *reinterpret_cast<const uint2*>(
            &g_xTh[(size_t)__float_as_int(ra.x) * NCH + col]);
        const uint2 p1 = *reinterpret_cast<const uint2*>(
            &g_xTh[(size_t)__float_as_int(ra.z) * NCH + col]);
        const uint2 p2 = *reinterpret_cast<const uint2*>(
            &g_xTh[(size_t)__float_as_int(rb.x) * NCH + col]);
        const uint2 p3 = *reinterpret_cast<const uint2*>(
            &g_xTh[(size_t)__float_as_int(rb.z) * NCH + col]);
        const uint2 p4 = *reinterpret_cast<const uint2*>(
            &g_xTh[(size_t)__float_as_int(rc.x) * NCH + col]);
        const uint2 p5 = *reinterpret_cast<const uint2*>(
            &g_xTh[(size_t)__float_as_int(rc.z) * NCH + col]);
        const uint2 p6 = *reinterpret_cast<const uint2*>(
            &g_xTh[(size_t)__float_as_int(rd.x) * NCH + col]);
        const uint2 p7 = *reinterpret_cast<const uint2*>(
            &g_xTh[(size_t)__float_as_int(rd.z) * NCH + col]);

        float2 f;
        f = __half22float2(*reinterpret_cast<const __half2*>(&p0.x));
        a0.x += f.x * ra.y; a0.y += f.y * ra.y;
        f = __half22float2(*reinterpret_cast<const __half2*>(&p0.y));
        a0.z += f.x * ra.y; a0.w += f.y * ra.y;
        f = __half22float2(*reinterpret_cast<const __half2*>(&p1.x));
        a1.x += f.x * ra.w; a1.y += f.y * ra.w;
        f = __half22float2(*reinterpret_cast<const __half2*>(&p1.y));
        a1.z += f.x * ra.w; a1.w += f.y * ra.w;

        f = __half22float2(*reinterpret_cast<const __half2*>(&p2.x));
        a0.x += f.x * rb.y; a0.y += f.y * rb.y;
        f = __half22float2(*reinterpret_cast<const __half2*>(&p2.y));
        a0.z += f.x * rb.y; a0.w += f.y * rb.y;
        f = __half22float2(*reinterpret_cast<const __half2*>(&p3.x));
        a1.x += f.x * rb.w; a1.y += f.y * rb.w;
        f = __half22float2(*reinterpret_cast<const __half2*>(&p3.y));
        a1.z += f.x * rb.w; a1.w += f.y * rb.w;

        f = __half22float2(*reinterpret_cast<const __half2*>(&p4.x));
        a0.x += f.x * rc.y; a0.y += f.y * rc.y;
        f = __half22float2(*reinterpret_cast<const __half2*>(&p4.y));
        a0.z += f.x * rc.y; a0.w += f.y * rc.y;
        f = __half22float2(*reinterpret_cast<const __half2*>(&p5.x));
        a1.x += f.x * rc.w; a1.y += f.y * rc.w;
        f = __half22float2(*reinterpret_cast<const __half2*>(&p5.y));
        a1.z += f.x * rc.w; a1.w += f.y * rc.w;

        f = __half22float2(*reinterpret_cast<const __half2*>(&p6.x));
        a0.x += f.x * rd.y; a0.y += f.y * rd.y;
        f = __half22float2(*reinterpret_cast<const __half2*>(&p6.y));
        a0.z += f.x * rd.y; a0.w += f.y * rd.y;
        f = __half22float2(*reinterpret_cast<const __half2*>(&p7.x));
        a1.x += f.x * rd.w; a1.y += f.y * rd.w;
        f = __half22float2(*reinterpret_cast<const __half2*>(&p7.y));
        a1.z += f.x * rd.w; a1.w += f.y * rd.w;
    }
    for (; i < n; i++) {
        float2 r0 = rec[i];
        const uint2 p0 = *reinterpret_cast<const uint2*>(
            &g_xTh[(size_t)__float_as_int(r0.x) * NCH + col]);
        float2 f;
        f = __half22float2(*reinterpret_cast<const __half2*>(&p0.x));
        a0.x += f.x * r0.y; a0.y += f.y * r0.y;
        f = __half22float2(*reinterpret_cast<const __half2*>(&p0.y));
        a0.z += f.x * r0.y; a0.w += f.y * r0.y;
    }
    a0.x += a1.x; a0.y += a1.y; a0.z += a1.z; a0.w += a1.w;

    // Stage [8 bins][128 ch] in smem, then write out[ch][s0..s0+7] coalesced.
    __shared__ float sm[8][128];
    *reinterpret_cast<float4*>(&sm[warp][lane * 4]) = a0;
    __syncthreads();

    if (threadIdx.x < 128) {
        const int ch = threadIdx.x;
        const int s0 = blockIdx.x * 8;
        float4 o0 = make_float4(sm[0][ch], sm[1][ch], sm[2][ch], sm[3][ch]);
        float4 o1 = make_float4(sm[4][ch], sm[5][ch], sm[6][ch], sm[7][ch]);
        float4* dst = reinterpret_cast<float4*>(&out[(size_t)ch * S + s0]);
        dst[0] = o0;
        dst[1] = o1;
    }
}

// ---------------------------------------------------------------------------
extern "C" void kernel_launch(void* const* d_in, const int* in_sizes, int n_in,
                              void* d_out, int out_size) {
    const float* x      = (const float*)d_in[0];  // [128][262144] flat
    const int*   ht     = (const int*)d_in[1];
    const int*   sp     = (const int*)d_in[2];
    const float* w      = (const float*)d_in[3];
    float*       out    = (float*)d_out;          // [128][32768] flat
    const int    nvotes = in_sizes[1];

    // 1) Zero bucket cursors (must precede fused kernel's atomics).
    zero_cursor_kernel<<<(S + 255) / 256, 256>>>();

    // 2) Fused transpose+convert AND vote scatter (independent work overlapped).
    {
        const int nblocks = 8192;                       // (HW/128) * (NCH/32)
        const int vpb = (nvotes + nblocks - 1) / nblocks;  // 184 <= 256
        fused_transpose_scatter_kernel<<<nblocks, 256>>>(x, ht, sp, w, nvotes, vpb);
    }

    // 3) Per-bin register accumulation (R6-proven loop) + fused output transpose.
    accum_kernel<<<S / 8, 256>>>(out);
}